// round 1
// baseline (speedup 1.0000x reference)
#include <cuda_runtime.h>

// Problem shape (fixed by the dataset)
#define BB 64
#define LL 4096
#define EE 256
#define HH 256
#define SPLITS 16
#define LC (LL / SPLITS)     // 256 rows per split
#define NW 8                 // warps per CTA in k1

// Scratch (no allocations allowed in kernel_launch)
__device__ float g_Wh[BB * EE];                 // 64 KB
__device__ float g_pm[BB * SPLITS];             // split max
__device__ float g_pd[BB * SPLITS];             // split denom
__device__ float g_pctx[BB * SPLITS * EE];      // 1 MB split contexts

// -------------------------------------------------------------------------
// k0: Wh[b,e] = sum_h W[e,h] * hidden[b,h]
// grid = B, block = 256 (thread t owns e = t). W (256 KB) stays L2-resident.
// -------------------------------------------------------------------------
__global__ void k0_wh(const float* __restrict__ W, const float* __restrict__ hidden) {
    __shared__ float hs[HH];
    const int b = blockIdx.x;
    const int t = threadIdx.x;
    hs[t] = hidden[b * HH + t];
    __syncthreads();

    const float4* Wr = reinterpret_cast<const float4*>(W + (size_t)t * HH);
    const float4* hv = reinterpret_cast<const float4*>(hs);
    float acc = 0.f;
#pragma unroll 16
    for (int i = 0; i < HH / 4; i++) {
        float4 w = Wr[i];
        float4 h = hv[i];
        acc += w.x * h.x + w.y * h.y + w.z * h.z + w.w * h.w;
    }
    g_Wh[b * EE + t] = acc;
}

// -------------------------------------------------------------------------
// k1: single pass over enc. One CTA = (split s, batch b), 8 warps.
// Warp processes rows l = s*LC + w, w+8, ... Each lane holds 8 enc floats
// (e = lane*4..lane*4+3 and 128+lane*4..+3) -> 2x LDG.128, coalesced.
// Online softmax with rescale-on-new-max only.
// -------------------------------------------------------------------------
__global__ __launch_bounds__(256) void k1_pass(const float* __restrict__ enc) {
    const int s = blockIdx.x;
    const int b = blockIdx.y;
    const int t = threadIdx.x;
    const int w = t >> 5;
    const int lane = t & 31;

    __shared__ float4 wh_s[EE / 4];          // 64 float4
    __shared__ float sm_m[NW];
    __shared__ float sm_d[NW];
    __shared__ float sm_ctx[NW][EE];         // 8 KB

    if (t < EE / 4)
        wh_s[t] = reinterpret_cast<const float4*>(g_Wh + b * EE)[t];
    __syncthreads();

    const float4 wh0 = wh_s[lane];
    const float4 wh1 = wh_s[lane + 32];

    const float4* encb = reinterpret_cast<const float4*>(enc)
                       + (size_t)b * LL * (EE / 4)
                       + (size_t)s * LC * (EE / 4);

    float m = -1e30f, d = 0.f;
    float4 c0 = make_float4(0.f, 0.f, 0.f, 0.f);
    float4 c1 = make_float4(0.f, 0.f, 0.f, 0.f);

    // prefetch first row
    const float4* pr = encb + (size_t)w * (EE / 4);
    float4 v0 = pr[lane];
    float4 v1 = pr[lane + 32];

    for (int l = w; l < LC; l += NW) {
        float4 n0 = v0, n1 = v1;
        if (l + NW < LC) {
            const float4* pn = encb + (size_t)(l + NW) * (EE / 4);
            n0 = pn[lane];
            n1 = pn[lane + 32];
        }

        // dot(enc_row, Wh)
        float p = v0.x * wh0.x + v0.y * wh0.y + v0.z * wh0.z + v0.w * wh0.w
                + v1.x * wh1.x + v1.y * wh1.y + v1.z * wh1.z + v1.w * wh1.w;
        p += __shfl_xor_sync(0xffffffffu, p, 16);
        p += __shfl_xor_sync(0xffffffffu, p, 8);
        p += __shfl_xor_sync(0xffffffffu, p, 4);
        p += __shfl_xor_sync(0xffffffffu, p, 2);
        p += __shfl_xor_sync(0xffffffffu, p, 1);

        // online softmax update
        if (p > m) {
            const float sc = __expf(m - p);
            d *= sc;
            c0.x *= sc; c0.y *= sc; c0.z *= sc; c0.w *= sc;
            c1.x *= sc; c1.y *= sc; c1.z *= sc; c1.w *= sc;
            m = p;
        }
        const float e = __expf(p - m);
        d += e;
        c0.x += e * v0.x; c0.y += e * v0.y; c0.z += e * v0.z; c0.w += e * v0.w;
        c1.x += e * v1.x; c1.y += e * v1.y; c1.z += e * v1.z; c1.w += e * v1.w;

        v0 = n0;
        v1 = n1;
    }

    // CTA-level combine
    if (lane == 0) { sm_m[w] = m; sm_d[w] = d; }
    __syncthreads();

    float M = sm_m[0];
#pragma unroll
    for (int i = 1; i < NW; i++) M = fmaxf(M, sm_m[i]);
    float D = 0.f;
#pragma unroll
    for (int i = 0; i < NW; i++) D += sm_d[i] * __expf(sm_m[i] - M);

    const float sc = __expf(m - M);   // m is uniform across the warp
    sm_ctx[w][lane * 4 + 0] = c0.x * sc;
    sm_ctx[w][lane * 4 + 1] = c0.y * sc;
    sm_ctx[w][lane * 4 + 2] = c0.z * sc;
    sm_ctx[w][lane * 4 + 3] = c0.w * sc;
    sm_ctx[w][128 + lane * 4 + 0] = c1.x * sc;
    sm_ctx[w][128 + lane * 4 + 1] = c1.y * sc;
    sm_ctx[w][128 + lane * 4 + 2] = c1.z * sc;
    sm_ctx[w][128 + lane * 4 + 3] = c1.w * sc;
    __syncthreads();

    float acc = 0.f;
#pragma unroll
    for (int i = 0; i < NW; i++) acc += sm_ctx[i][t];

    const int idx = b * SPLITS + s;
    g_pctx[(size_t)idx * EE + t] = acc;
    if (t == 0) { g_pm[idx] = M; g_pd[idx] = D; }
}

// -------------------------------------------------------------------------
// k2: combine splits; out[b,e] = sum_s ctx_s[e]*exp(m_s - M) / D
// -------------------------------------------------------------------------
__global__ void k2_combine(float* __restrict__ out) {
    const int b = blockIdx.x;
    const int t = threadIdx.x;
    __shared__ float sm[SPLITS];
    __shared__ float sd[SPLITS];
    if (t < SPLITS) {
        sm[t] = g_pm[b * SPLITS + t];
        sd[t] = g_pd[b * SPLITS + t];
    }
    __syncthreads();

    float M = sm[0];
#pragma unroll
    for (int i = 1; i < SPLITS; i++) M = fmaxf(M, sm[i]);
    float D = 0.f;
#pragma unroll
    for (int i = 0; i < SPLITS; i++) D += sd[i] * __expf(sm[i] - M);

    float acc = 0.f;
#pragma unroll
    for (int i = 0; i < SPLITS; i++)
        acc += g_pctx[(size_t)(b * SPLITS + i) * EE + t] * __expf(sm[i] - M);

    out[b * EE + t] = acc / D;
}

// -------------------------------------------------------------------------
// Inputs (metadata order): hidden [B,H] f32, encoderhidden [B,L,E] f32,
// W [E,H] f32, b [1] f32 (softmax-invariant -> ignored).
// Output: context [B,E] f32.
// -------------------------------------------------------------------------
extern "C" void kernel_launch(void* const* d_in, const int* in_sizes, int n_in,
                              void* d_out, int out_size) {
    const float* hidden = (const float*)d_in[0];
    const float* enc    = (const float*)d_in[1];
    const float* W      = (const float*)d_in[2];
    float* out          = (float*)d_out;

    k0_wh<<<BB, 256>>>(W, hidden);
    k1_pass<<<dim3(SPLITS, BB), 256>>>(enc);
    k2_combine<<<BB, EE>>>(out);
}

// round 4
// speedup vs baseline: 1.2287x; 1.2287x over previous
#include <cuda_runtime.h>

// Problem shape (fixed by the dataset)
#define BB 64
#define LL 4096
#define EE 256
#define HH 256
#define SPLITS 32
#define LC (LL / SPLITS)     // 128 rows per split
#define NW 8                 // warps per CTA in k1

// Scratch (no allocations allowed in kernel_launch)
__device__ float g_Wh[BB * EE];                 // 64 KB
__device__ float g_pm[BB * SPLITS];             // split max
__device__ float g_pd[BB * SPLITS];             // split denom
__device__ float g_pctx[BB * SPLITS * EE];      // 2 MB split contexts

// -------------------------------------------------------------------------
// k0: Wh[b,e] = sum_h W[e,h] * hidden[b,h]
// One warp per (b, e). Lane loads 2 coalesced float4 of the W row, dots
// against smem-resident hidden[b], butterfly-reduce, lane 0 writes.
// grid = (EE/8, BB), block = 256 (8 warps).
// -------------------------------------------------------------------------
__global__ __launch_bounds__(256) void k0_wh(const float* __restrict__ W,
                                             const float* __restrict__ hidden) {
    __shared__ float hs[HH];
    const int b = blockIdx.y;
    const int t = threadIdx.x;
    const int w = t >> 5;
    const int lane = t & 31;

    hs[t] = hidden[b * HH + t];
    __syncthreads();

    const int e = blockIdx.x * NW + w;
    const float4* Wr = reinterpret_cast<const float4*>(W + (size_t)e * HH);
    const float4* hv = reinterpret_cast<const float4*>(hs);

    const float4 w0 = Wr[lane];
    const float4 w1 = Wr[lane + 32];
    const float4 h0 = hv[lane];
    const float4 h1 = hv[lane + 32];

    float p = w0.x * h0.x + w0.y * h0.y + w0.z * h0.z + w0.w * h0.w
            + w1.x * h1.x + w1.y * h1.y + w1.z * h1.z + w1.w * h1.w;
    p += __shfl_xor_sync(0xffffffffu, p, 16);
    p += __shfl_xor_sync(0xffffffffu, p, 8);
    p += __shfl_xor_sync(0xffffffffu, p, 4);
    p += __shfl_xor_sync(0xffffffffu, p, 2);
    p += __shfl_xor_sync(0xffffffffu, p, 1);

    if (lane == 0) g_Wh[b * EE + e] = p;
}

// -------------------------------------------------------------------------
// k1: single pass over enc. One CTA = (split s, batch b), 8 warps.
// Warp processes rows l = w, w+8, ... of its 128-row chunk. Each lane holds
// 8 enc floats (2x LDG.128 streaming, coalesced). Online softmax with
// rescale-on-new-max only.
// -------------------------------------------------------------------------
__global__ __launch_bounds__(256) void k1_pass(const float* __restrict__ enc) {
    const int s = blockIdx.x;
    const int b = blockIdx.y;
    const int t = threadIdx.x;
    const int w = t >> 5;
    const int lane = t & 31;

    __shared__ float4 wh_s[EE / 4];          // 64 float4
    __shared__ float sm_m[NW];
    __shared__ float sm_d[NW];
    __shared__ float sm_ctx[NW][EE];         // 8 KB

    if (t < EE / 4)
        wh_s[t] = reinterpret_cast<const float4*>(g_Wh + b * EE)[t];
    __syncthreads();

    const float4 wh0 = wh_s[lane];
    const float4 wh1 = wh_s[lane + 32];

    const float4* encb = reinterpret_cast<const float4*>(enc)
                       + (size_t)b * LL * (EE / 4)
                       + (size_t)s * LC * (EE / 4);

    float m = -1e30f, d = 0.f;
    float4 c0 = make_float4(0.f, 0.f, 0.f, 0.f);
    float4 c1 = make_float4(0.f, 0.f, 0.f, 0.f);

    // prefetch first row (streaming: enc is read exactly once)
    const float4* pr = encb + (size_t)w * (EE / 4);
    float4 v0 = __ldcs(pr + lane);
    float4 v1 = __ldcs(pr + lane + 32);

    for (int l = w; l < LC; l += NW) {
        float4 n0 = v0, n1 = v1;
        if (l + NW < LC) {
            const float4* pn = encb + (size_t)(l + NW) * (EE / 4);
            n0 = __ldcs(pn + lane);
            n1 = __ldcs(pn + lane + 32);
        }

        // dot(enc_row, Wh)
        float p = v0.x * wh0.x + v0.y * wh0.y + v0.z * wh0.z + v0.w * wh0.w
                + v1.x * wh1.x + v1.y * wh1.y + v1.z * wh1.z + v1.w * wh1.w;
        p += __shfl_xor_sync(0xffffffffu, p, 16);
        p += __shfl_xor_sync(0xffffffffu, p, 8);
        p += __shfl_xor_sync(0xffffffffu, p, 4);
        p += __shfl_xor_sync(0xffffffffu, p, 2);
        p += __shfl_xor_sync(0xffffffffu, p, 1);

        // online softmax update (rare branch: only on new max)
        if (p > m) {
            const float sc = __expf(m - p);
            d *= sc;
            c0.x *= sc; c0.y *= sc; c0.z *= sc; c0.w *= sc;
            c1.x *= sc; c1.y *= sc; c1.z *= sc; c1.w *= sc;
            m = p;
        }
        const float e = __expf(p - m);
        d += e;
        c0.x += e * v0.x; c0.y += e * v0.y; c0.z += e * v0.z; c0.w += e * v0.w;
        c1.x += e * v1.x; c1.y += e * v1.y; c1.z += e * v1.z; c1.w += e * v1.w;

        v0 = n0;
        v1 = n1;
    }

    // CTA-level combine
    if (lane == 0) { sm_m[w] = m; sm_d[w] = d; }
    __syncthreads();

    float M = sm_m[0];
#pragma unroll
    for (int i = 1; i < NW; i++) M = fmaxf(M, sm_m[i]);
    float D = 0.f;
#pragma unroll
    for (int i = 0; i < NW; i++) D += sm_d[i] * __expf(sm_m[i] - M);

    const float sc = __expf(m - M);   // m is uniform across the warp
    sm_ctx[w][lane * 4 + 0] = c0.x * sc;
    sm_ctx[w][lane * 4 + 1] = c0.y * sc;
    sm_ctx[w][lane * 4 + 2] = c0.z * sc;
    sm_ctx[w][lane * 4 + 3] = c0.w * sc;
    sm_ctx[w][128 + lane * 4 + 0] = c1.x * sc;
    sm_ctx[w][128 + lane * 4 + 1] = c1.y * sc;
    sm_ctx[w][128 + lane * 4 + 2] = c1.z * sc;
    sm_ctx[w][128 + lane * 4 + 3] = c1.w * sc;
    __syncthreads();

    float acc = 0.f;
#pragma unroll
    for (int i = 0; i < NW; i++) acc += sm_ctx[i][t];

    const int idx = b * SPLITS + s;
    g_pctx[(size_t)idx * EE + t] = acc;
    if (t == 0) { g_pm[idx] = M; g_pd[idx] = D; }
}

// -------------------------------------------------------------------------
// k2: combine splits; out[b,e] = sum_s ctx_s[e]*exp(m_s - M) / D
// -------------------------------------------------------------------------
__global__ void k2_combine(float* __restrict__ out) {
    const int b = blockIdx.x;
    const int t = threadIdx.x;
    __shared__ float sm[SPLITS];
    __shared__ float sd[SPLITS];
    if (t < SPLITS) {
        sm[t] = g_pm[b * SPLITS + t];
        sd[t] = g_pd[b * SPLITS + t];
    }
    __syncthreads();

    float M = sm[0];
#pragma unroll
    for (int i = 1; i < SPLITS; i++) M = fmaxf(M, sm[i]);
    float D = 0.f;
#pragma unroll
    for (int i = 0; i < SPLITS; i++) D += sd[i] * __expf(sm[i] - M);

    float acc = 0.f;
#pragma unroll
    for (int i = 0; i < SPLITS; i++)
        acc += g_pctx[(size_t)(b * SPLITS + i) * EE + t] * __expf(sm[i] - M);

    out[b * EE + t] = acc / D;
}

// -------------------------------------------------------------------------
// Inputs (metadata order): hidden [B,H] f32, encoderhidden [B,L,E] f32,
// W [E,H] f32, b [1] f32 (softmax-invariant -> ignored).
// Output: context [B,E] f32.
// -------------------------------------------------------------------------
extern "C" void kernel_launch(void* const* d_in, const int* in_sizes, int n_in,
                              void* d_out, int out_size) {
    const float* hidden = (const float*)d_in[0];
    const float* enc    = (const float*)d_in[1];
    const float* W      = (const float*)d_in[2];
    float* out          = (float*)d_out;

    k0_wh<<<dim3(EE / NW, BB), 256>>>(W, hidden);
    k1_pass<<<dim3(SPLITS, BB), 256>>>(enc);
    k2_combine<<<BB, EE>>>(out);
}

// round 6
// speedup vs baseline: 1.3293x; 1.0818x over previous
#include <cuda_runtime.h>

// Problem shape (fixed by the dataset)
#define BB 64
#define LL 4096
#define EE 256
#define HH 256
#define SPLITS 9             // 64*9 = 576 CTAs = one wave at 4 CTAs/SM
#define NW 8                 // warps per CTA in k1

// Scratch (no allocations allowed in kernel_launch)
__device__ float g_Wh[BB * EE];
__device__ float g_pm[BB * SPLITS];
__device__ float g_pd[BB * SPLITS];
__device__ float g_pctx[BB * SPLITS * EE];
__device__ int   g_cnt[BB];

// -------------------------------------------------------------------------
// k0: Wh[b,e] = sum_h W[e,h] * hidden[b,h]. One warp per (b,e).
// Also zeroes the per-batch completion counters for the fused combine.
// grid = (EE/8, BB), block = 256.
// -------------------------------------------------------------------------
__global__ __launch_bounds__(256) void k0_wh(const float* __restrict__ W,
                                             const float* __restrict__ hidden) {
    const int b = blockIdx.y;
    const int t = threadIdx.x;
    const int w = t >> 5;
    const int lane = t & 31;

    if (blockIdx.x == 0 && t == 0) g_cnt[b] = 0;

    const int e = blockIdx.x * NW + w;
    const float4* Wr = reinterpret_cast<const float4*>(W + (size_t)e * HH);
    const float4* hv = reinterpret_cast<const float4*>(hidden + (size_t)b * HH);

    const float4 w0 = __ldg(Wr + lane);
    const float4 w1 = __ldg(Wr + lane + 32);
    const float4 h0 = __ldg(hv + lane);
    const float4 h1 = __ldg(hv + lane + 32);

    float p = w0.x * h0.x + w0.y * h0.y + w0.z * h0.z + w0.w * h0.w
            + w1.x * h1.x + w1.y * h1.y + w1.z * h1.z + w1.w * h1.w;
    p += __shfl_xor_sync(0xffffffffu, p, 16);
    p += __shfl_xor_sync(0xffffffffu, p, 8);
    p += __shfl_xor_sync(0xffffffffu, p, 4);
    p += __shfl_xor_sync(0xffffffffu, p, 2);
    p += __shfl_xor_sync(0xffffffffu, p, 1);

    if (lane == 0) g_Wh[b * EE + e] = p;
}

// -------------------------------------------------------------------------
// k1: single pass over enc + fused split-combine.
// One CTA = (split s, batch b), 8 warps, single wave (576 CTAs).
// Warp processes row pairs (l, l+8), stride 16: two independent shuffle
// reduction chains interleave -> halved exposed latency, 8 LDG.128 in
// flight per warp. Online softmax with rescale-on-new-max.
// Last CTA per batch (atomic counter) combines all splits and writes out.
// -------------------------------------------------------------------------
__global__ __launch_bounds__(256, 4) void k1_pass(const float* __restrict__ enc,
                                                  float* __restrict__ out) {
    const int s = blockIdx.x;
    const int b = blockIdx.y;
    const int t = threadIdx.x;
    const int w = t >> 5;
    const int lane = t & 31;

    __shared__ float4 wh_s[EE / 4];
    __shared__ float sm_m[NW];
    __shared__ float sm_d[NW];
    __shared__ float sm_ctx[NW][EE];
    __shared__ int s_last;

    if (t < EE / 4)
        wh_s[t] = reinterpret_cast<const float4*>(g_Wh + b * EE)[t];
    __syncthreads();

    const float4 wh0 = wh_s[lane];
    const float4 wh1 = wh_s[lane + 32];

    const float4* encb = reinterpret_cast<const float4*>(enc)
                       + (size_t)b * LL * (EE / 4);

    const int begin = (s * LL) / SPLITS;
    const int end   = ((s + 1) * LL) / SPLITS;

    float m = -1e30f, d = 0.f;
    float4 c0 = make_float4(0.f, 0.f, 0.f, 0.f);
    float4 c1 = make_float4(0.f, 0.f, 0.f, 0.f);

    int  l  = begin + w;
    bool hA = l < end;
    bool hB = l + 8 < end;
    float4 a0, a1, b0, b1;
    if (hA) {
        const float4* p0 = encb + (size_t)l * (EE / 4);
        a0 = __ldcs(p0 + lane);
        a1 = __ldcs(p0 + lane + 32);
    }
    if (hB) {
        const float4* p1 = encb + (size_t)(l + 8) * (EE / 4);
        b0 = __ldcs(p1 + lane);
        b1 = __ldcs(p1 + lane + 32);
    }

    while (hA) {
        // prefetch next pair
        const int nl = l + 16;
        const bool nA = nl < end;
        const bool nB = nl + 8 < end;
        float4 na0, na1, nb0, nb1;
        if (nA) {
            const float4* p0 = encb + (size_t)nl * (EE / 4);
            na0 = __ldcs(p0 + lane);
            na1 = __ldcs(p0 + lane + 32);
        }
        if (nB) {
            const float4* p1 = encb + (size_t)(nl + 8) * (EE / 4);
            nb0 = __ldcs(p1 + lane);
            nb1 = __ldcs(p1 + lane + 32);
        }

        // partial dots for both rows
        float pA = a0.x * wh0.x + a0.y * wh0.y + a0.z * wh0.z + a0.w * wh0.w
                 + a1.x * wh1.x + a1.y * wh1.y + a1.z * wh1.z + a1.w * wh1.w;
        float pB = 0.f;
        if (hB)
            pB = b0.x * wh0.x + b0.y * wh0.y + b0.z * wh0.z + b0.w * wh0.w
               + b1.x * wh1.x + b1.y * wh1.y + b1.z * wh1.z + b1.w * wh1.w;

        // two independent butterfly chains (interleaved by the scheduler)
        pA += __shfl_xor_sync(0xffffffffu, pA, 16);
        pB += __shfl_xor_sync(0xffffffffu, pB, 16);
        pA += __shfl_xor_sync(0xffffffffu, pA, 8);
        pB += __shfl_xor_sync(0xffffffffu, pB, 8);
        pA += __shfl_xor_sync(0xffffffffu, pA, 4);
        pB += __shfl_xor_sync(0xffffffffu, pB, 4);
        pA += __shfl_xor_sync(0xffffffffu, pA, 2);
        pB += __shfl_xor_sync(0xffffffffu, pB, 2);
        pA += __shfl_xor_sync(0xffffffffu, pA, 1);
        pB += __shfl_xor_sync(0xffffffffu, pB, 1);

        // online softmax update: row A
        if (pA > m) {
            const float sc = __expf(m - pA);
            d *= sc;
            c0.x *= sc; c0.y *= sc; c0.z *= sc; c0.w *= sc;
            c1.x *= sc; c1.y *= sc; c1.z *= sc; c1.w *= sc;
            m = pA;
        }
        {
            const float e = __expf(pA - m);
            d += e;
            c0.x += e * a0.x; c0.y += e * a0.y; c0.z += e * a0.z; c0.w += e * a0.w;
            c1.x += e * a1.x; c1.y += e * a1.y; c1.z += e * a1.z; c1.w += e * a1.w;
        }
        // row B
        if (hB) {
            if (pB > m) {
                const float sc = __expf(m - pB);
                d *= sc;
                c0.x *= sc; c0.y *= sc; c0.z *= sc; c0.w *= sc;
                c1.x *= sc; c1.y *= sc; c1.z *= sc; c1.w *= sc;
                m = pB;
            }
            const float e = __expf(pB - m);
            d += e;
            c0.x += e * b0.x; c0.y += e * b0.y; c0.z += e * b0.z; c0.w += e * b0.w;
            c1.x += e * b1.x; c1.y += e * b1.y; c1.z += e * b1.z; c1.w += e * b1.w;
        }

        a0 = na0; a1 = na1; b0 = nb0; b1 = nb1;
        hA = nA; hB = nB; l = nl;
    }

    // CTA-level combine
    if (lane == 0) { sm_m[w] = m; sm_d[w] = d; }
    __syncthreads();

    float M = sm_m[0];
#pragma unroll
    for (int i = 1; i < NW; i++) M = fmaxf(M, sm_m[i]);
    float D = 0.f;
#pragma unroll
    for (int i = 0; i < NW; i++) D += sm_d[i] * __expf(sm_m[i] - M);

    const float sc = __expf(m - M);   // m is warp-uniform (butterfly leaves full sum in all lanes)
    sm_ctx[w][lane * 4 + 0] = c0.x * sc;
    sm_ctx[w][lane * 4 + 1] = c0.y * sc;
    sm_ctx[w][lane * 4 + 2] = c0.z * sc;
    sm_ctx[w][lane * 4 + 3] = c0.w * sc;
    sm_ctx[w][128 + lane * 4 + 0] = c1.x * sc;
    sm_ctx[w][128 + lane * 4 + 1] = c1.y * sc;
    sm_ctx[w][128 + lane * 4 + 2] = c1.z * sc;
    sm_ctx[w][128 + lane * 4 + 3] = c1.w * sc;
    __syncthreads();

    float acc = 0.f;
#pragma unroll
    for (int i = 0; i < NW; i++) acc += sm_ctx[i][t];

    const int idx = b * SPLITS + s;
    g_pctx[(size_t)idx * EE + t] = acc;
    if (t == 0) { g_pm[idx] = M; g_pd[idx] = D; }

    // ---- fused split-combine: last CTA of this batch finishes the output ----
    __threadfence();
    if (t == 0) {
        const int old = atomicAdd(&g_cnt[b], 1);
        s_last = (old == SPLITS - 1);
    }
    __syncthreads();
    if (!s_last) return;
    __threadfence();   // acquire: make other CTAs' partials visible

    float pm[SPLITS];
#pragma unroll
    for (int i = 0; i < SPLITS; i++) pm[i] = g_pm[b * SPLITS + i];
    float Mg = pm[0];
#pragma unroll
    for (int i = 1; i < SPLITS; i++) Mg = fmaxf(Mg, pm[i]);
    float Dg = 0.f;
#pragma unroll
    for (int i = 0; i < SPLITS; i++) Dg += g_pd[b * SPLITS + i] * __expf(pm[i] - Mg);

    float accg = 0.f;
#pragma unroll
    for (int i = 0; i < SPLITS; i++)
        accg += g_pctx[(size_t)(b * SPLITS + i) * EE + t] * __expf(pm[i] - Mg);

    out[b * EE + t] = accg / Dg;
}

// -------------------------------------------------------------------------
// Inputs (metadata order): hidden [B,H] f32, encoderhidden [B,L,E] f32,
// W [E,H] f32, b [1] f32 (softmax-invariant -> ignored).
// Output: context [B,E] f32.
// -------------------------------------------------------------------------
extern "C" void kernel_launch(void* const* d_in, const int* in_sizes, int n_in,
                              void* d_out, int out_size) {
    const float* hidden = (const float*)d_in[0];
    const float* enc    = (const float*)d_in[1];
    const float* W      = (const float*)d_in[2];
    float* out          = (float*)d_out;

    k0_wh<<<dim3(EE / NW, BB), 256>>>(W, hidden);
    k1_pass<<<dim3(SPLITS, BB), 256>>>(enc, out);
}